// round 5
// baseline (speedup 1.0000x reference)
#include <cuda_runtime.h>
#include <math.h>

#define NN 100000
#define FD 128
#define OUTF 64
#define EMAX 1600000
#define SCHUNK 512
#define NBLKMAX ((NN + SCHUNK - 1) / SCHUNK)

// Scratch (static __device__ to satisfy no-alloc rule)
__device__ float g_bufA[NN * FD];   // hs (layer1, UNSCALED) ; reused later? no: stays hs
__device__ float g_bufB[NN * FD];   // ts (layer2 output, pre-scaled by dinv)
__device__ int   g_cnt[NN];
__device__ int   g_partial[NN];
__device__ int   g_rowptr[NN + 1];
__device__ int   g_rowcur[NN];
__device__ float g_dinv[NN];
__device__ int   g_esrc[EMAX];
__device__ int   g_bsum[NBLKMAX];
__device__ int   g_boff[NBLKMAX];

// ---- packed f32x2 helpers (sm_100+) ----
__device__ __forceinline__ unsigned long long pk2(float v) {
    unsigned long long r;
    asm("mov.b64 %0,{%1,%1};" : "=l"(r) : "f"(v));
    return r;
}
__device__ __forceinline__ float2 upk2(unsigned long long v) {
    float2 r;
    asm("mov.b64 {%0,%1},%2;" : "=f"(r.x), "=f"(r.y) : "l"(v));
    return r;
}
__device__ __forceinline__ unsigned long long ffma2(unsigned long long a,
                                                    unsigned long long b,
                                                    unsigned long long c) {
    unsigned long long d;
    asm("fma.rn.f32x2 %0,%1,%2,%3;" : "=l"(d) : "l"(a), "l"(b), "l"(c));
    return d;
}

// ================= GEMM core (device inline) =================
// Computes 4 rows per warp of X(row,128) @ Wsm(128x128), X rows in xs (smem).
// Accumulators returned via acc[8] (4 rows x 2 ull each holding cols 4l..4l+3).
__device__ __forceinline__ void gemm_rows4(const float* __restrict__ xs,
                                           const float* __restrict__ Wsm,
                                           int lane,
                                           unsigned long long acc[8]) {
#pragma unroll
    for (int i = 0; i < 8; i++) acc[i] = 0ull;
    const ulonglong2* Wp = (const ulonglong2*)Wsm;
#pragma unroll 4
    for (int k = 0; k < FD; k++) {
        ulonglong2 w = Wp[k * (FD / 4) + lane];
        unsigned long long p0 = pk2(xs[k]);
        unsigned long long p1 = pk2(xs[FD + k]);
        unsigned long long p2 = pk2(xs[2 * FD + k]);
        unsigned long long p3 = pk2(xs[3 * FD + k]);
        acc[0] = ffma2(p0, w.x, acc[0]);  acc[1] = ffma2(p0, w.y, acc[1]);
        acc[2] = ffma2(p1, w.x, acc[2]);  acc[3] = ffma2(p1, w.y, acc[3]);
        acc[4] = ffma2(p2, w.x, acc[4]);  acc[5] = ffma2(p2, w.y, acc[5]);
        acc[6] = ffma2(p3, w.x, acc[6]);  acc[7] = ffma2(p3, w.y, acc[7]);
    }
}

// ========== K0: GEMM1 half A (unscaled) + edge degree count ==========
__global__ void k_gemmA_count(const float* __restrict__ A,
                              const float* __restrict__ W1,
                              const int* __restrict__ dst,
                              float* __restrict__ out,
                              int nA, int GA, int E) {
    if ((int)blockIdx.x >= GA) {
        // count blocks
        int stride = (gridDim.x - GA) * blockDim.x;
        for (int e = (blockIdx.x - GA) * blockDim.x + threadIdx.x; e < E; e += stride)
            atomicAdd(&g_cnt[dst[e]], 1);
        return;
    }
    extern __shared__ float smem[];
    float* Wsm = smem;
    float* Xs  = smem + FD * FD;
    for (int idx = threadIdx.x; idx < FD * FD; idx += blockDim.x)
        Wsm[idx] = W1[idx];
    __syncthreads();

    int warp = threadIdx.x >> 5, lane = threadIdx.x & 31;
    int row0 = blockIdx.x * 32 + warp * 4;
    float* xs = Xs + warp * (4 * FD);
#pragma unroll
    for (int r = 0; r < 4; r++) {
        int row = row0 + r;
        float4 v = make_float4(0.f, 0.f, 0.f, 0.f);
        if (row < nA) v = ((const float4*)A)[row * (FD / 4) + lane];
        ((float4*)(xs + r * FD))[lane] = v;
    }
    __syncwarp();
    unsigned long long acc[8];
    gemm_rows4(xs, Wsm, lane, acc);
#pragma unroll
    for (int r = 0; r < 4; r++) {
        int row = row0 + r;
        if (row >= nA) break;
        float2 lo = upk2(acc[2 * r]), hi = upk2(acc[2 * r + 1]);
        ((float4*)out)[row * (FD / 4) + lane] = make_float4(lo.x, lo.y, hi.x, hi.y);
    }
}

// ========== scans ==========
__global__ void k_scan1(int n) {
    __shared__ int sm[SCHUNK];
    int i = blockIdx.x * SCHUNK + threadIdx.x;
    int v = (i < n) ? g_cnt[i] : 0;
    sm[threadIdx.x] = v;
    __syncthreads();
    for (int off = 1; off < SCHUNK; off <<= 1) {
        int t = (threadIdx.x >= (unsigned)off) ? sm[threadIdx.x - off] : 0;
        __syncthreads();
        sm[threadIdx.x] += t;
        __syncthreads();
    }
    if (i < n) g_partial[i] = sm[threadIdx.x];
    if (threadIdx.x == SCHUNK - 1) g_bsum[blockIdx.x] = sm[threadIdx.x];
}

__global__ void k_scan2(int nblk) {
    __shared__ int sm[SCHUNK];
    int t = threadIdx.x;
    int mine = (t < nblk) ? g_bsum[t] : 0;
    sm[t] = mine;
    __syncthreads();
    for (int off = 1; off < SCHUNK; off <<= 1) {
        int v = (t >= off) ? sm[t - off] : 0;
        __syncthreads();
        sm[t] += v;
        __syncthreads();
    }
    if (t < nblk) g_boff[t] = sm[t] - mine;   // exclusive
}

__global__ void k_rows(int n, int E) {
    int i = blockIdx.x * blockDim.x + threadIdx.x;
    if (i < n) {
        int c = g_cnt[i];
        int rp = g_partial[i] + g_boff[i / SCHUNK] - c;
        g_rowptr[i] = rp;
        g_rowcur[i] = rp;
        g_dinv[i] = rsqrtf((float)(c + 1));   // self-loop -> deg >= 1
        if (i == 0) g_rowptr[n] = E;
    }
}

// ========== K_mid: GEMM1 half B (unscaled) + CSR scatter ==========
__global__ void k_gemmB_scatter(const float* __restrict__ A,
                                const float* __restrict__ W1,
                                const int* __restrict__ src,
                                const int* __restrict__ dst,
                                float* __restrict__ out,
                                int nA, int n, int GB, int E) {
    if ((int)blockIdx.x >= GB) {
        int stride = (gridDim.x - GB) * blockDim.x;
        for (int e = (blockIdx.x - GB) * blockDim.x + threadIdx.x; e < E; e += stride) {
            int d = dst[e];
            int pos = atomicAdd(&g_rowcur[d], 1);
            g_esrc[pos] = src[e];
        }
        return;
    }
    extern __shared__ float smem[];
    float* Wsm = smem;
    float* Xs  = smem + FD * FD;
    for (int idx = threadIdx.x; idx < FD * FD; idx += blockDim.x)
        Wsm[idx] = W1[idx];
    __syncthreads();

    int warp = threadIdx.x >> 5, lane = threadIdx.x & 31;
    int row0 = nA + blockIdx.x * 32 + warp * 4;
    float* xs = Xs + warp * (4 * FD);
#pragma unroll
    for (int r = 0; r < 4; r++) {
        int row = row0 + r;
        float4 v = make_float4(0.f, 0.f, 0.f, 0.f);
        if (row < n) v = ((const float4*)A)[row * (FD / 4) + lane];
        ((float4*)(xs + r * FD))[lane] = v;
    }
    __syncwarp();
    unsigned long long acc[8];
    gemm_rows4(xs, Wsm, lane, acc);
#pragma unroll
    for (int r = 0; r < 4; r++) {
        int row = row0 + r;
        if (row >= n) break;
        float2 lo = upk2(acc[2 * r]), hi = upk2(acc[2 * r + 1]);
        ((float4*)out)[row * (FD / 4) + lane] = make_float4(lo.x, lo.y, hi.x, hi.y);
    }
}

// ========== fused: aggregate layer1 + GEMM2 (Wmu|Wls) ==========
// For each node d: H[d] = dinv[d]*( hs[d]*dinv[d] + sum_src hs[src]*dinv[src] ) + b1
// then ts[d] = dinv[d] * (H[d] @ Wcat), written to out.
__global__ void k_agg1_gemm2(const float* __restrict__ S,      // hs unscaled
                             const float* __restrict__ b1,
                             const float* __restrict__ Wmu,
                             const float* __restrict__ Wls,
                             float* __restrict__ out, int n) {
    extern __shared__ float smem[];
    float* Wsm = smem;
    float* Xs  = smem + FD * FD;

    for (int idx = threadIdx.x; idx < FD * FD; idx += blockDim.x) {
        int k = idx >> 7, j = idx & 127;
        Wsm[idx] = (j < OUTF) ? Wmu[(k << 6) + j] : Wls[(k << 6) + (j - OUTF)];
    }
    __syncthreads();

    int warp = threadIdx.x >> 5, lane = threadIdx.x & 31;
    int row0 = blockIdx.x * 32 + warp * 4;
    float* xs = Xs + warp * (4 * FD);
    const float4* Sv = (const float4*)S;
    float4 bv = ((const float4*)b1)[lane];

#pragma unroll
    for (int r = 0; r < 4; r++) {
        int row = row0 + r;
        if (row < n) {
            int beg = g_rowptr[row], end = g_rowptr[row + 1];
            float dd = g_dinv[row];
            float4 sv = Sv[row * 32 + lane];
            float4 a = make_float4(sv.x * dd, sv.y * dd, sv.z * dd, sv.w * dd);
#pragma unroll 4
            for (int e = beg; e < end; e++) {
                int s = __ldg(&g_esrc[e]);
                float ds = __ldg(&g_dinv[s]);
                float4 v = Sv[s * 32 + lane];
                a.x = fmaf(v.x, ds, a.x);
                a.y = fmaf(v.y, ds, a.y);
                a.z = fmaf(v.z, ds, a.z);
                a.w = fmaf(v.w, ds, a.w);
            }
            ((float4*)(xs + r * FD))[lane] =
                make_float4(a.x * dd + bv.x, a.y * dd + bv.y,
                            a.z * dd + bv.z, a.w * dd + bv.w);
        } else {
            ((float4*)(xs + r * FD))[lane] = make_float4(0.f, 0.f, 0.f, 0.f);
        }
    }
    __syncwarp();

    unsigned long long acc[8];
    gemm_rows4(xs, Wsm, lane, acc);

#pragma unroll
    for (int r = 0; r < 4; r++) {
        int row = row0 + r;
        if (row >= n) break;
        float sc = g_dinv[row];
        float2 lo = upk2(acc[2 * r]), hi = upk2(acc[2 * r + 1]);
        ((float4*)out)[row * (FD / 4) + lane] =
            make_float4(lo.x * sc, lo.y * sc, hi.x * sc, hi.y * sc);
    }
}

// ========== aggregation 2 + reparametrize ==========
// S rows pre-scaled by dinv[src]; layout [mu(64)|logstd(64)].
__global__ void k_agg2(const float* __restrict__ S,
                       const float* __restrict__ bmu,
                       const float* __restrict__ bls,
                       const float* __restrict__ initd,
                       float* __restrict__ out, int n) {
    int gw = (blockIdx.x * blockDim.x + threadIdx.x) >> 5;
    if (gw >= n) return;
    int lane = threadIdx.x & 31;
    const float4* Sv = (const float4*)S;
    int beg = g_rowptr[gw], end = g_rowptr[gw + 1];
    float4 a = Sv[gw * 32 + lane];
#pragma unroll 4
    for (int e = beg; e < end; e++) {
        int s = __ldg(&g_esrc[e]);
        float4 v = Sv[s * 32 + lane];
        a.x += v.x; a.y += v.y; a.z += v.z; a.w += v.w;
    }
    float sc = g_dinv[gw];
    a.x *= sc; a.y *= sc; a.z *= sc; a.w *= sc;

    float ox = __shfl_xor_sync(0xffffffffu, a.x, 16);
    float oy = __shfl_xor_sync(0xffffffffu, a.y, 16);
    float oz = __shfl_xor_sync(0xffffffffu, a.z, 16);
    float ow = __shfl_xor_sync(0xffffffffu, a.w, 16);

    if (lane < 16) {
        float4 bm = ((const float4*)bmu)[lane];
        float4 bl = ((const float4*)bls)[lane];
        float4 iv = ((const float4*)initd)[gw * 16 + lane];
        float4 r;
        r.x = (a.x + bm.x) + iv.x * expf(ox + bl.x);
        r.y = (a.y + bm.y) + iv.y * expf(oy + bl.y);
        r.z = (a.z + bm.z) + iv.z * expf(oz + bl.z);
        r.w = (a.w + bm.w) + iv.w * expf(ow + bl.w);
        ((float4*)out)[gw * 16 + lane] = r;
    }
}

#define SMEM_GEMM ((FD * FD + 8 * 4 * FD) * (int)sizeof(float))

extern "C" void kernel_launch(void* const* d_in, const int* in_sizes, int n_in,
                              void* d_out, int out_size) {
    const float* x     = (const float*)d_in[0];
    const int*   ei    = (const int*)d_in[1];
    const float* initd = (const float*)d_in[2];
    const float* W1    = (const float*)d_in[3];
    const float* b1    = (const float*)d_in[4];
    const float* Wmu   = (const float*)d_in[5];
    const float* bmu   = (const float*)d_in[6];
    const float* Wls   = (const float*)d_in[7];
    const float* bls   = (const float*)d_in[8];
    float* out = (float*)d_out;

    int n = in_sizes[0] / FD;
    int E = in_sizes[1] / 2;
    const int* src = ei;
    const int* dst = ei + E;

    void *pA = nullptr, *pB = nullptr, *pC = nullptr;
    cudaGetSymbolAddress(&pA, g_bufA);
    cudaGetSymbolAddress(&pB, g_bufB);
    cudaGetSymbolAddress(&pC, g_cnt);
    float* bufA = (float*)pA;
    float* bufB = (float*)pB;

    cudaFuncSetAttribute(k_gemmA_count,  cudaFuncAttributeMaxDynamicSharedMemorySize, SMEM_GEMM);
    cudaFuncSetAttribute(k_gemmB_scatter, cudaFuncAttributeMaxDynamicSharedMemorySize, SMEM_GEMM);
    cudaFuncSetAttribute(k_agg1_gemm2,   cudaFuncAttributeMaxDynamicSharedMemorySize, SMEM_GEMM);

    // split GEMM1 rows: half A before scan, half B overlapped with scatter
    int nA = ((n / 2 + 31) / 32) * 32;
    if (nA > n) nA = n;
    int GA = nA / 32;
    int GB = (n - nA + 31) / 32;
    const int CB = 512;   // count blocks
    const int SB = 512;   // scatter blocks

    cudaMemsetAsync(pC, 0, n * sizeof(int));

    // K0: GEMM1[0:nA) + degree count (overlapped)
    k_gemmA_count<<<GA + CB, 256, SMEM_GEMM>>>(x, W1, dst, bufA, nA, GA, E);

    int nblk = (n + SCHUNK - 1) / SCHUNK;
    k_scan1<<<nblk, SCHUNK>>>(n);
    k_scan2<<<1, SCHUNK>>>(nblk);
    k_rows<<<(n + 255) / 256, 256>>>(n, E);

    // K_mid: GEMM1[nA:n) + CSR scatter (overlapped)
    k_gemmB_scatter<<<GB + SB, 256, SMEM_GEMM>>>(x, W1, src, dst, bufA, nA, n, GB, E);

    // fused: aggregate layer1 + GEMM2 -> ts (pre-scaled) in bufB
    k_agg1_gemm2<<<(n + 31) / 32, 256, SMEM_GEMM>>>(bufA, b1, Wmu, Wls, bufB, n);

    // aggregate layer2 + reparametrize
    k_agg2<<<(n * 32 + 255) / 256, 256>>>(bufB, bmu, bls, initd, out, n);
}

// round 7
// speedup vs baseline: 1.3958x; 1.3958x over previous
#include <cuda_runtime.h>
#include <math.h>

#define NN 100000
#define FD 128
#define OUTF 64
#define EMAX 1600000
#define SCHUNK 512
#define NBLKMAX ((NN + SCHUNK - 1) / SCHUNK)

typedef unsigned long long ull;

// Scratch (static __device__ to satisfy no-alloc rule)
__device__ float g_bufA[NN * FD];
__device__ float g_bufB[NN * FD];
__device__ int   g_cnt[NN];
__device__ int   g_partial[NN];
__device__ int   g_rowptr[NN + 1];
__device__ int   g_rowcur[NN];
__device__ float g_dinv[NN];
__device__ int   g_esrc[EMAX];
__device__ int   g_bsum[NBLKMAX];
__device__ int   g_boff[NBLKMAX];

// ---- packed f32x2 helpers (sm_100+) ----
__device__ __forceinline__ ull pk2(float v) {
    ull r;
    asm("mov.b64 %0,{%1,%1};" : "=l"(r) : "f"(v));
    return r;
}
__device__ __forceinline__ float2 upk2(ull v) {
    float2 r;
    asm("mov.b64 {%0,%1},%2;" : "=f"(r.x), "=f"(r.y) : "l"(v));
    return r;
}
__device__ __forceinline__ ull ffma2(ull a, ull b, ull c) {
    ull d;
    asm("fma.rn.f32x2 %0,%1,%2,%3;" : "=l"(d) : "l"(a), "l"(b), "l"(c));
    return d;
}

// ---------- graph prep ----------
__global__ void k_count(const int* __restrict__ dst, int E) {
    int e = blockIdx.x * blockDim.x + threadIdx.x;
    if (e < E) atomicAdd(&g_cnt[dst[e]], 1);
}

__global__ void k_scan1(int n) {
    __shared__ int sm[SCHUNK];
    int i = blockIdx.x * SCHUNK + threadIdx.x;
    int v = (i < n) ? g_cnt[i] : 0;
    sm[threadIdx.x] = v;
    __syncthreads();
    for (int off = 1; off < SCHUNK; off <<= 1) {
        int t = (threadIdx.x >= (unsigned)off) ? sm[threadIdx.x - off] : 0;
        __syncthreads();
        sm[threadIdx.x] += t;
        __syncthreads();
    }
    if (i < n) g_partial[i] = sm[threadIdx.x];
    if (threadIdx.x == SCHUNK - 1) g_bsum[blockIdx.x] = sm[threadIdx.x];
}

__global__ void k_scan2(int nblk) {
    __shared__ int sm[SCHUNK];
    int t = threadIdx.x;
    int mine = (t < nblk) ? g_bsum[t] : 0;
    sm[t] = mine;
    __syncthreads();
    for (int off = 1; off < SCHUNK; off <<= 1) {
        int v = (t >= off) ? sm[t - off] : 0;
        __syncthreads();
        sm[t] += v;
        __syncthreads();
    }
    if (t < nblk) g_boff[t] = sm[t] - mine;   // exclusive
}

__global__ void k_rows(int n, int E) {
    int i = blockIdx.x * blockDim.x + threadIdx.x;
    if (i < n) {
        int c = g_cnt[i];
        int rp = g_partial[i] + g_boff[i / SCHUNK] - c;
        g_rowptr[i] = rp;
        g_rowcur[i] = rp;
        g_dinv[i] = rsqrtf((float)(c + 1));   // self-loop -> deg >= 1
        if (i == 0) g_rowptr[n] = E;
    }
}

__global__ void k_scatter(const int* __restrict__ src, const int* __restrict__ dst, int E) {
    int e = blockIdx.x * blockDim.x + threadIdx.x;
    if (e < E) {
        int d = dst[e];
        int pos = atomicAdd(&g_rowcur[d], 1);
        g_esrc[pos] = src[e];
    }
}

// ---------- GEMM: out[i] = (scaled? dinv[i]:1) * (A[i] @ W) ----------
// 8 warps x 8 rows = 64 rows/block. FMA-pipe-bound inner loop:
// per k4: 4x LDS.128 (W) + 8x LDS.128 broadcast (X) = 12 wavefronts vs 64 FFMA2.
__global__ __launch_bounds__(256, 2)
void k_gemm(const float* __restrict__ A,
            const float* __restrict__ Wa,
            const float* __restrict__ Wb,
            int concat, int scaled,
            float* __restrict__ out, int n) {
    extern __shared__ float smem[];
    float* Wsm = smem;                    // 128*128
    float* Xs  = smem + FD * FD;          // 8 warps * 8 rows * 128

    for (int idx = threadIdx.x; idx < FD * FD; idx += blockDim.x) {
        float w;
        if (concat) {
            int k = idx >> 7, j = idx & 127;
            w = (j < OUTF) ? Wa[(k << 6) + j] : Wb[(k << 6) + (j - OUTF)];
        } else {
            w = Wa[idx];
        }
        Wsm[idx] = w;
    }
    __syncthreads();

    int warp = threadIdx.x >> 5, lane = threadIdx.x & 31;
    int row0 = blockIdx.x * 64 + warp * 8;
    float* xs = Xs + warp * (8 * FD);

#pragma unroll
    for (int r = 0; r < 8; r++) {
        int row = row0 + r;
        float4 v = make_float4(0.f, 0.f, 0.f, 0.f);
        if (row < n) v = ((const float4*)A)[row * (FD / 4) + lane];
        ((float4*)(xs + r * FD))[lane] = v;
    }
    __syncwarp();

    ull acc[16];
#pragma unroll
    for (int i = 0; i < 16; i++) acc[i] = 0ull;
    const ulonglong2* Wp = (const ulonglong2*)Wsm;

#pragma unroll 1
    for (int k4 = 0; k4 < FD; k4 += 4) {
        ulonglong2 w0 = Wp[(k4 + 0) * (FD / 4) + lane];
        ulonglong2 w1 = Wp[(k4 + 1) * (FD / 4) + lane];
        ulonglong2 w2 = Wp[(k4 + 2) * (FD / 4) + lane];
        ulonglong2 w3 = Wp[(k4 + 3) * (FD / 4) + lane];
#pragma unroll
        for (int r = 0; r < 8; r++) {
            float4 xv = ((const float4*)(xs + r * FD))[k4 >> 2];
            ull px = pk2(xv.x), py = pk2(xv.y), pz = pk2(xv.z), pw = pk2(xv.w);
            acc[2 * r]     = ffma2(px, w0.x, acc[2 * r]);
            acc[2 * r + 1] = ffma2(px, w0.y, acc[2 * r + 1]);
            acc[2 * r]     = ffma2(py, w1.x, acc[2 * r]);
            acc[2 * r + 1] = ffma2(py, w1.y, acc[2 * r + 1]);
            acc[2 * r]     = ffma2(pz, w2.x, acc[2 * r]);
            acc[2 * r + 1] = ffma2(pz, w2.y, acc[2 * r + 1]);
            acc[2 * r]     = ffma2(pw, w3.x, acc[2 * r]);
            acc[2 * r + 1] = ffma2(pw, w3.y, acc[2 * r + 1]);
        }
    }

#pragma unroll
    for (int r = 0; r < 8; r++) {
        int row = row0 + r;
        if (row >= n) break;
        float sc = scaled ? g_dinv[row] : 1.0f;
        float2 lo = upk2(acc[2 * r]), hi = upk2(acc[2 * r + 1]);
        ((float4*)out)[row * (FD / 4) + lane] =
            make_float4(lo.x * sc, lo.y * sc, hi.x * sc, hi.y * sc);
    }
}

// ---------- aggregation 1 ----------
// S = hs UNSCALED.  out[d] = dinv[d]*( dinv[d]*hs[d] + sum_src dinv[src]*hs[src] ) + b1
__global__ void k_agg1(const float* __restrict__ S,
                       const float* __restrict__ bias,
                       float* __restrict__ out, int n) {
    int gw = (blockIdx.x * blockDim.x + threadIdx.x) >> 5;
    if (gw >= n) return;
    int lane = threadIdx.x & 31;
    const float4* Sv = (const float4*)S;
    int beg = g_rowptr[gw], end = g_rowptr[gw + 1];
    float dd = g_dinv[gw];
    float4 sv = Sv[gw * 32 + lane];
    float4 a = make_float4(sv.x * dd, sv.y * dd, sv.z * dd, sv.w * dd);
#pragma unroll 4
    for (int e = beg; e < end; e++) {
        int s = __ldg(&g_esrc[e]);
        float ds = __ldg(&g_dinv[s]);
        float4 v = Sv[s * 32 + lane];
        a.x = fmaf(v.x, ds, a.x);
        a.y = fmaf(v.y, ds, a.y);
        a.z = fmaf(v.z, ds, a.z);
        a.w = fmaf(v.w, ds, a.w);
    }
    float4 b = ((const float4*)bias)[lane];
    ((float4*)out)[gw * 32 + lane] =
        make_float4(a.x * dd + b.x, a.y * dd + b.y, a.z * dd + b.z, a.w * dd + b.w);
}

// ---------- aggregation 2 + reparametrize ----------
// S rows pre-scaled by dinv[src]; layout [mu(64)|logstd(64)].
__global__ void k_agg2(const float* __restrict__ S,
                       const float* __restrict__ bmu,
                       const float* __restrict__ bls,
                       const float* __restrict__ initd,
                       float* __restrict__ out, int n) {
    int gw = (blockIdx.x * blockDim.x + threadIdx.x) >> 5;
    if (gw >= n) return;
    int lane = threadIdx.x & 31;
    const float4* Sv = (const float4*)S;
    int beg = g_rowptr[gw], end = g_rowptr[gw + 1];
    float4 a = Sv[gw * 32 + lane];
#pragma unroll 4
    for (int e = beg; e < end; e++) {
        int s = __ldg(&g_esrc[e]);
        float4 v = Sv[s * 32 + lane];
        a.x += v.x; a.y += v.y; a.z += v.z; a.w += v.w;
    }
    float sc = g_dinv[gw];
    a.x *= sc; a.y *= sc; a.z *= sc; a.w *= sc;

    float ox = __shfl_xor_sync(0xffffffffu, a.x, 16);
    float oy = __shfl_xor_sync(0xffffffffu, a.y, 16);
    float oz = __shfl_xor_sync(0xffffffffu, a.z, 16);
    float ow = __shfl_xor_sync(0xffffffffu, a.w, 16);

    if (lane < 16) {
        float4 bm = ((const float4*)bmu)[lane];
        float4 bl = ((const float4*)bls)[lane];
        float4 iv = ((const float4*)initd)[gw * 16 + lane];
        float4 r;
        r.x = (a.x + bm.x) + iv.x * expf(ox + bl.x);
        r.y = (a.y + bm.y) + iv.y * expf(oy + bl.y);
        r.z = (a.z + bm.z) + iv.z * expf(oz + bl.z);
        r.w = (a.w + bm.w) + iv.w * expf(ow + bl.w);
        ((float4*)out)[gw * 16 + lane] = r;
    }
}

#define SMEM_GEMM ((FD * FD + 8 * 8 * FD) * (int)sizeof(float))

extern "C" void kernel_launch(void* const* d_in, const int* in_sizes, int n_in,
                              void* d_out, int out_size) {
    const float* x     = (const float*)d_in[0];
    const int*   ei    = (const int*)d_in[1];
    const float* initd = (const float*)d_in[2];
    const float* W1    = (const float*)d_in[3];
    const float* b1    = (const float*)d_in[4];
    const float* Wmu   = (const float*)d_in[5];
    const float* bmu   = (const float*)d_in[6];
    const float* Wls   = (const float*)d_in[7];
    const float* bls   = (const float*)d_in[8];
    float* out = (float*)d_out;

    int n = in_sizes[0] / FD;
    int E = in_sizes[1] / 2;
    const int* src = ei;
    const int* dst = ei + E;

    void *pA = nullptr, *pB = nullptr, *pC = nullptr;
    cudaGetSymbolAddress(&pA, g_bufA);
    cudaGetSymbolAddress(&pB, g_bufB);
    cudaGetSymbolAddress(&pC, g_cnt);
    float* bufA = (float*)pA;
    float* bufB = (float*)pB;

    cudaFuncSetAttribute(k_gemm, cudaFuncAttributeMaxDynamicSharedMemorySize, SMEM_GEMM);

    int nblk = (n + SCHUNK - 1) / SCHUNK;

    // prep (gemm1 slotted at kernel index 3 so ncu captures it)
    cudaMemsetAsync(pC, 0, n * sizeof(int));
    k_count<<<(E + 255) / 256, 256>>>(dst, E);            // 0
    k_scan1<<<nblk, SCHUNK>>>(n);                         // 1
    k_scan2<<<1, SCHUNK>>>(nblk);                         // 2

    // GEMM1: hs = x @ W1 (UNSCALED) — independent of graph prep
    k_gemm<<<(n + 63) / 64, 256, SMEM_GEMM>>>(x, W1, nullptr, 0, 0, bufA, n);  // 3

    k_rows<<<(n + 255) / 256, 256>>>(n, E);               // 4
    k_scatter<<<(E + 255) / 256, 256>>>(src, dst, E);     // 5

    // agg1: H = dinv.*(scatter dinv[s]*hs[s] + dinv*hs) + b1
    k_agg1<<<(n * 32 + 255) / 256, 256>>>(bufA, b1, bufB, n);   // 6

    // GEMM2: ts = dinv .* (H @ [Wmu|Wls])
    k_gemm<<<(n + 63) / 64, 256, SMEM_GEMM>>>(bufB, Wmu, Wls, 1, 1, bufA, n);  // 7

    // agg2 + reparametrize
    k_agg2<<<(n * 32 + 255) / 256, 256>>>(bufA, bmu, bls, initd, out, n);      // 8
}

// round 8
// speedup vs baseline: 1.4665x; 1.0507x over previous
#include <cuda_runtime.h>
#include <math.h>

#define NN 100000
#define FD 128
#define OUTF 64
#define EMAX 1600000
#define SCHUNK 512
#define NBLKMAX ((NN + SCHUNK - 1) / SCHUNK)

typedef unsigned long long ull;

// Scratch (static __device__ to satisfy no-alloc rule)
__device__ float g_bufA[NN * FD];
__device__ float g_bufB[NN * FD];
__device__ int   g_cnt[NN];
__device__ int   g_partial[NN];
__device__ int   g_rowptr[NN + 1];
__device__ int   g_rowcur[NN];
__device__ float g_dinv[NN];
__device__ int   g_esrc[EMAX];
__device__ int   g_bsum[NBLKMAX];
__device__ int   g_boff[NBLKMAX];

// ---- packed f32x2 helpers (sm_100+) ----
__device__ __forceinline__ ull pk2(float v) {
    ull r;
    asm("mov.b64 %0,{%1,%1};" : "=l"(r) : "f"(v));
    return r;
}
__device__ __forceinline__ float2 upk2(ull v) {
    float2 r;
    asm("mov.b64 {%0,%1},%2;" : "=f"(r.x), "=f"(r.y) : "l"(v));
    return r;
}
__device__ __forceinline__ ull ffma2(ull a, ull b, ull c) {
    ull d;
    asm("fma.rn.f32x2 %0,%1,%2,%3;" : "=l"(d) : "l"(a), "l"(b), "l"(c));
    return d;
}

// ---------- graph prep ----------
__global__ void k_count(const int* __restrict__ dst, int E) {
    int e = blockIdx.x * blockDim.x + threadIdx.x;
    if (e < E) atomicAdd(&g_cnt[dst[e]], 1);
}

__global__ void k_scan1(int n) {
    __shared__ int sm[SCHUNK];
    int i = blockIdx.x * SCHUNK + threadIdx.x;
    int v = (i < n) ? g_cnt[i] : 0;
    sm[threadIdx.x] = v;
    __syncthreads();
    for (int off = 1; off < SCHUNK; off <<= 1) {
        int t = (threadIdx.x >= (unsigned)off) ? sm[threadIdx.x - off] : 0;
        __syncthreads();
        sm[threadIdx.x] += t;
        __syncthreads();
    }
    if (i < n) g_partial[i] = sm[threadIdx.x];
    if (threadIdx.x == SCHUNK - 1) g_bsum[blockIdx.x] = sm[threadIdx.x];
}

__global__ void k_scan2(int nblk) {
    __shared__ int sm[SCHUNK];
    int t = threadIdx.x;
    int mine = (t < nblk) ? g_bsum[t] : 0;
    sm[t] = mine;
    __syncthreads();
    for (int off = 1; off < SCHUNK; off <<= 1) {
        int v = (t >= off) ? sm[t - off] : 0;
        __syncthreads();
        sm[t] += v;
        __syncthreads();
    }
    if (t < nblk) g_boff[t] = sm[t] - mine;   // exclusive
}

__global__ void k_rows(int n, int E) {
    int i = blockIdx.x * blockDim.x + threadIdx.x;
    if (i < n) {
        int c = g_cnt[i];
        int rp = g_partial[i] + g_boff[i / SCHUNK] - c;
        g_rowptr[i] = rp;
        g_rowcur[i] = rp;
        g_dinv[i] = rsqrtf((float)(c + 1));   // self-loop -> deg >= 1
        if (i == 0) g_rowptr[n] = E;
    }
}

__global__ void k_scatter(const int* __restrict__ src, const int* __restrict__ dst, int E) {
    int e = blockIdx.x * blockDim.x + threadIdx.x;
    if (e < E) {
        int d = dst[e];
        int pos = atomicAdd(&g_rowcur[d], 1);
        g_esrc[pos] = src[e];
    }
}

// ---------- GEMM ----------
// Block: 64 rows x 64 cols (blockIdx.y selects col-half / W matrix).
// smem: As 64x128 fp32 (rows XOR-swizzled in 16B units) = 32KB, Ws 128x64 = 32KB.
// Warps 2(row)x4(col) -> warp tile 32x16; lane (lr=lane/4, lc=lane&3) -> 4 rows x 4 cols.
// Per k4 per warp: 8 LDS.128 (all 1-wavefront) vs 32 FFMA2 -> fma-bound with 3 CTAs/SM.
__global__ __launch_bounds__(256, 3)
void k_gemm(const float* __restrict__ A,
            const float* __restrict__ WA,
            const float* __restrict__ WB,
            int ldW, int scaled,
            float* __restrict__ out, int n) {
    extern __shared__ float smem[];
    float* As = smem;              // 64 * 128
    float* Ws = smem + 64 * FD;    // 128 * 64
    const float* Wg = (blockIdx.y == 0) ? WA : WB;
    int tid = threadIdx.x;
    int rowBase = blockIdx.x * 64;

    // stage W half (coalesced): Ws[k][0..63]
#pragma unroll
    for (int p = 0; p < 8; p++) {
        int idx = tid + p * 256;          // 2048 float4 slots
        int k = idx >> 4, cq = idx & 15;
        ((float4*)Ws)[idx] = ((const float4*)(Wg + k * ldW))[cq];
    }
    // stage A rows, swizzled: As[row][ (k4 ^ ((row>>2)&7)) *4 .. ]
#pragma unroll
    for (int p = 0; p < 8; p++) {
        int idx = tid + p * 256;
        int row = idx >> 5, k4 = idx & 31;
        int gr = rowBase + row;
        float4 v = make_float4(0.f, 0.f, 0.f, 0.f);
        if (gr < n) v = ((const float4*)A)[gr * 32 + k4];
        ((float4*)(As + row * FD))[k4 ^ ((row >> 2) & 7)] = v;
    }
    __syncthreads();

    int warp = tid >> 5, lane = tid & 31;
    int wr = warp & 1, wc = warp >> 1;    // wc: 0..3
    int lr = lane >> 2, lc = lane & 3;
    int rbase = wr * 32 + lr * 4;
    int aswz = lr;                        // ((rbase+j)>>2)&7 == lr for j=0..3
    int wcol = wc * 4 + lc;               // float4 index within 16

    const float4* As0 = (const float4*)(As + (rbase + 0) * FD);
    const float4* As1 = (const float4*)(As + (rbase + 1) * FD);
    const float4* As2 = (const float4*)(As + (rbase + 2) * FD);
    const float4* As3 = (const float4*)(As + (rbase + 3) * FD);

    ull acc[8];
#pragma unroll
    for (int i = 0; i < 8; i++) acc[i] = 0ull;

#pragma unroll 4
    for (int k4 = 0; k4 < 32; k4++) {
        float4 a0 = As0[k4 ^ aswz];
        float4 a1 = As1[k4 ^ aswz];
        float4 a2 = As2[k4 ^ aswz];
        float4 a3 = As3[k4 ^ aswz];
        const float* a0f = (const float*)&a0;
        const float* a1f = (const float*)&a1;
        const float* a2f = (const float*)&a2;
        const float* a3f = (const float*)&a3;
#pragma unroll
        for (int kk = 0; kk < 4; kk++) {
            ulonglong2 w = ((const ulonglong2*)(Ws + (4 * k4 + kk) * 64))[wcol];
            ull p0 = pk2(a0f[kk]);
            ull p1 = pk2(a1f[kk]);
            ull p2 = pk2(a2f[kk]);
            ull p3 = pk2(a3f[kk]);
            acc[0] = ffma2(p0, w.x, acc[0]);  acc[1] = ffma2(p0, w.y, acc[1]);
            acc[2] = ffma2(p1, w.x, acc[2]);  acc[3] = ffma2(p1, w.y, acc[3]);
            acc[4] = ffma2(p2, w.x, acc[4]);  acc[5] = ffma2(p2, w.y, acc[5]);
            acc[6] = ffma2(p3, w.x, acc[6]);  acc[7] = ffma2(p3, w.y, acc[7]);
        }
    }

#pragma unroll
    for (int j = 0; j < 4; j++) {
        int gr = rowBase + rbase + j;
        if (gr < n) {
            float sc = scaled ? g_dinv[gr] : 1.0f;
            float2 lo = upk2(acc[2 * j]), hi = upk2(acc[2 * j + 1]);
            ((float4*)out)[gr * 32 + blockIdx.y * 16 + wcol] =
                make_float4(lo.x * sc, lo.y * sc, hi.x * sc, hi.y * sc);
        }
    }
}

// ---------- aggregation 1 ----------
// S = hs UNSCALED.  out[d] = dinv[d]*( dinv[d]*hs[d] + sum_src dinv[src]*hs[src] ) + b1
__global__ void k_agg1(const float* __restrict__ S,
                       const float* __restrict__ bias,
                       float* __restrict__ out, int n) {
    int gw = (blockIdx.x * blockDim.x + threadIdx.x) >> 5;
    if (gw >= n) return;
    int lane = threadIdx.x & 31;
    const float4* Sv = (const float4*)S;
    int beg = g_rowptr[gw], end = g_rowptr[gw + 1];
    float dd = g_dinv[gw];
    float4 sv = Sv[gw * 32 + lane];
    float4 a = make_float4(sv.x * dd, sv.y * dd, sv.z * dd, sv.w * dd);
#pragma unroll 4
    for (int e = beg; e < end; e++) {
        int s = __ldg(&g_esrc[e]);
        float ds = __ldg(&g_dinv[s]);
        float4 v = Sv[s * 32 + lane];
        a.x = fmaf(v.x, ds, a.x);
        a.y = fmaf(v.y, ds, a.y);
        a.z = fmaf(v.z, ds, a.z);
        a.w = fmaf(v.w, ds, a.w);
    }
    float4 b = ((const float4*)bias)[lane];
    ((float4*)out)[gw * 32 + lane] =
        make_float4(a.x * dd + b.x, a.y * dd + b.y, a.z * dd + b.z, a.w * dd + b.w);
}

// ---------- aggregation 2 + reparametrize ----------
// S rows pre-scaled by dinv[src]; layout [mu(64)|logstd(64)].
__global__ void k_agg2(const float* __restrict__ S,
                       const float* __restrict__ bmu,
                       const float* __restrict__ bls,
                       const float* __restrict__ initd,
                       float* __restrict__ out, int n) {
    int gw = (blockIdx.x * blockDim.x + threadIdx.x) >> 5;
    if (gw >= n) return;
    int lane = threadIdx.x & 31;
    const float4* Sv = (const float4*)S;
    int beg = g_rowptr[gw], end = g_rowptr[gw + 1];
    float4 a = Sv[gw * 32 + lane];
#pragma unroll 4
    for (int e = beg; e < end; e++) {
        int s = __ldg(&g_esrc[e]);
        float4 v = Sv[s * 32 + lane];
        a.x += v.x; a.y += v.y; a.z += v.z; a.w += v.w;
    }
    float sc = g_dinv[gw];
    a.x *= sc; a.y *= sc; a.z *= sc; a.w *= sc;

    float ox = __shfl_xor_sync(0xffffffffu, a.x, 16);
    float oy = __shfl_xor_sync(0xffffffffu, a.y, 16);
    float oz = __shfl_xor_sync(0xffffffffu, a.z, 16);
    float ow = __shfl_xor_sync(0xffffffffu, a.w, 16);

    if (lane < 16) {
        float4 bm = ((const float4*)bmu)[lane];
        float4 bl = ((const float4*)bls)[lane];
        float4 iv = ((const float4*)initd)[gw * 16 + lane];
        float4 r;
        r.x = (a.x + bm.x) + iv.x * expf(ox + bl.x);
        r.y = (a.y + bm.y) + iv.y * expf(oy + bl.y);
        r.z = (a.z + bm.z) + iv.z * expf(oz + bl.z);
        r.w = (a.w + bm.w) + iv.w * expf(ow + bl.w);
        ((float4*)out)[gw * 16 + lane] = r;
    }
}

#define SMEM_GEMM ((64 * FD + FD * 64) * (int)sizeof(float))   // 64KB

extern "C" void kernel_launch(void* const* d_in, const int* in_sizes, int n_in,
                              void* d_out, int out_size) {
    const float* x     = (const float*)d_in[0];
    const int*   ei    = (const int*)d_in[1];
    const float* initd = (const float*)d_in[2];
    const float* W1    = (const float*)d_in[3];
    const float* b1    = (const float*)d_in[4];
    const float* Wmu   = (const float*)d_in[5];
    const float* bmu   = (const float*)d_in[6];
    const float* Wls   = (const float*)d_in[7];
    const float* bls   = (const float*)d_in[8];
    float* out = (float*)d_out;

    int n = in_sizes[0] / FD;
    int E = in_sizes[1] / 2;
    const int* src = ei;
    const int* dst = ei + E;

    void *pA = nullptr, *pB = nullptr, *pC = nullptr;
    cudaGetSymbolAddress(&pA, g_bufA);
    cudaGetSymbolAddress(&pB, g_bufB);
    cudaGetSymbolAddress(&pC, g_cnt);
    float* bufA = (float*)pA;
    float* bufB = (float*)pB;

    cudaFuncSetAttribute(k_gemm, cudaFuncAttributeMaxDynamicSharedMemorySize, SMEM_GEMM);

    int nblk = (n + SCHUNK - 1) / SCHUNK;
    dim3 ggrid((n + 63) / 64, 2);

    // Fork a NonBlocking stream so graph prep truly overlaps GEMM1.
    // Streams/events deliberately NOT destroyed: destroying a forked stream
    // mid-capture is illegal, and kernel_launch runs only a handful of times.
    cudaStream_t s2;
    cudaStreamCreateWithFlags(&s2, cudaStreamNonBlocking);
    cudaEvent_t evF, evJ;
    cudaEventCreateWithFlags(&evF, cudaEventDisableTiming);
    cudaEventCreateWithFlags(&evJ, cudaEventDisableTiming);

    cudaEventRecord(evF, 0);
    cudaStreamWaitEvent(s2, evF, 0);

    // prep chain on s2
    cudaMemsetAsync(pC, 0, n * sizeof(int), s2);                 // launch 1
    k_count<<<(E + 255) / 256, 256, 0, s2>>>(dst, E);            // 2
    k_scan1<<<nblk, SCHUNK, 0, s2>>>(n);                         // 3
    k_scan2<<<1, SCHUNK, 0, s2>>>(nblk);                         // 4

    // GEMM1 on default stream, concurrent with prep: hs = x @ W1 (unscaled)
    k_gemm<<<ggrid, 256, SMEM_GEMM>>>(x, W1, W1 + OUTF, FD, 0, bufA, n);  // 5 (ncu slot)

    k_rows<<<(n + 255) / 256, 256, 0, s2>>>(n, E);
    k_scatter<<<(E + 255) / 256, 256, 0, s2>>>(src, dst, E);

    cudaEventRecord(evJ, s2);
    cudaStreamWaitEvent(0, evJ, 0);

    // agg1: H = dinv.*(sum dinv[s]*hs[s] + dinv*hs) + b1
    k_agg1<<<(n * 32 + 255) / 256, 256>>>(bufA, b1, bufB, n);

    // GEMM2: ts = dinv .* (H @ [Wmu|Wls]) ; y=0 -> Wmu cols, y=1 -> Wls cols
    k_gemm<<<ggrid, 256, SMEM_GEMM>>>(bufB, Wmu, Wls, OUTF, 1, bufA, n);

    // agg2 + reparametrize
    k_agg2<<<(n * 32 + 255) / 256, 256>>>(bufA, bmu, bls, initd, out, n);
}

// round 9
// speedup vs baseline: 1.5783x; 1.0762x over previous
#include <cuda_runtime.h>
#include <math.h>

#define NN 100000
#define FD 128
#define OUTF 64
#define EMAX 1600000
#define SCHUNK 512
#define NBLKMAX ((NN + SCHUNK - 1) / SCHUNK)

typedef unsigned long long ull;

// Scratch (static __device__ to satisfy no-alloc rule)
__device__ float g_bufA[NN * FD];
__device__ float g_bufB[NN * FD];
__device__ int   g_cnt[NN];
__device__ int   g_partial[NN];
__device__ int   g_rowptr[NN + 1];
__device__ int   g_rowcur[NN];
__device__ float g_dinv[NN];
__device__ int   g_esrc[EMAX];
__device__ int   g_bsum[NBLKMAX];
__device__ int   g_boff[NBLKMAX];

// ---- packed f32x2 helpers (sm_100+) ----
__device__ __forceinline__ ull pk2(float v) {
    ull r;
    asm("mov.b64 %0,{%1,%1};" : "=l"(r) : "f"(v));
    return r;
}
__device__ __forceinline__ float2 upk2(ull v) {
    float2 r;
    asm("mov.b64 {%0,%1},%2;" : "=f"(r.x), "=f"(r.y) : "l"(v));
    return r;
}
__device__ __forceinline__ ull ffma2(ull a, ull b, ull c) {
    ull d;
    asm("fma.rn.f32x2 %0,%1,%2,%3;" : "=l"(d) : "l"(a), "l"(b), "l"(c));
    return d;
}

// ---------- graph prep ----------
__global__ void k_count(const int* __restrict__ dst, int E) {
    int e = blockIdx.x * blockDim.x + threadIdx.x;
    if (e < E) atomicAdd(&g_cnt[dst[e]], 1);
}

__global__ void k_scan1(int n) {
    __shared__ int sm[SCHUNK];
    int i = blockIdx.x * SCHUNK + threadIdx.x;
    int v = (i < n) ? g_cnt[i] : 0;
    sm[threadIdx.x] = v;
    __syncthreads();
    for (int off = 1; off < SCHUNK; off <<= 1) {
        int t = (threadIdx.x >= (unsigned)off) ? sm[threadIdx.x - off] : 0;
        __syncthreads();
        sm[threadIdx.x] += t;
        __syncthreads();
    }
    if (i < n) g_partial[i] = sm[threadIdx.x];
    if (threadIdx.x == SCHUNK - 1) g_bsum[blockIdx.x] = sm[threadIdx.x];
}

__global__ void k_scan2(int nblk) {
    __shared__ int sm[SCHUNK];
    int t = threadIdx.x;
    int mine = (t < nblk) ? g_bsum[t] : 0;
    sm[t] = mine;
    __syncthreads();
    for (int off = 1; off < SCHUNK; off <<= 1) {
        int v = (t >= off) ? sm[t - off] : 0;
        __syncthreads();
        sm[t] += v;
        __syncthreads();
    }
    if (t < nblk) g_boff[t] = sm[t] - mine;   // exclusive
}

__global__ void k_rows(int n, int E) {
    int i = blockIdx.x * blockDim.x + threadIdx.x;
    if (i < n) {
        int c = g_cnt[i];
        int rp = g_partial[i] + g_boff[i / SCHUNK] - c;
        g_rowptr[i] = rp;
        g_rowcur[i] = rp;
        g_dinv[i] = rsqrtf((float)(c + 1));   // self-loop -> deg >= 1
        if (i == 0) g_rowptr[n] = E;
    }
}

__global__ void k_scatter(const int* __restrict__ src, const int* __restrict__ dst, int E) {
    int e = blockIdx.x * blockDim.x + threadIdx.x;
    if (e < E) {
        int d = dst[e];
        int pos = atomicAdd(&g_rowcur[d], 1);
        g_esrc[pos] = src[e];
    }
}

// ---------- GEMM ----------
// Block tile: 64 rows x 128 cols. smem: As 64x128 (swizzled, 32KB) + Ws 128x128 (64KB).
// 8 warps = 2 row-groups x 4 col-groups -> warp tile 32r x 32c.
// Lane (lr=lane>>2, lc=lane&3): tile 4 rows x 8 cols -> 32 outputs/lane.
// Per lane per k: 4 A-floats + 8 W-floats = 48B smem for 32 FMAs (0.67 FMA/B).
__global__ __launch_bounds__(256, 2)
void k_gemm(const float* __restrict__ A,
            const float* __restrict__ WA,
            const float* __restrict__ WB,
            int ldW, int scaled,
            float* __restrict__ out, int n, int rowOff) {
    extern __shared__ float smem[];
    float* As = smem;              // 64 * 128
    float* Ws = smem + 64 * FD;    // 128 * 128
    int tid = threadIdx.x;
    int rowBase = rowOff + blockIdx.x * 64;

    // stage W (full 128x128): cols 0..63 from WA, 64..127 from WB
#pragma unroll
    for (int p = 0; p < 16; p++) {
        int idx = tid + p * 256;              // 4096 float4 slots
        int k = idx >> 5, cq = idx & 31;
        const float* Wg = (cq < 16) ? WA : WB;
        int c4 = cq & 15;
        ((float4*)Ws)[idx] = ((const float4*)(Wg + k * ldW))[c4];
    }
    // stage A rows, swizzled: float4 col index (k4 ^ ((row>>2)&7))
#pragma unroll
    for (int p = 0; p < 8; p++) {
        int idx = tid + p * 256;              // 2048 float4 slots
        int row = idx >> 5, k4 = idx & 31;
        int gr = rowBase + row;
        float4 v = make_float4(0.f, 0.f, 0.f, 0.f);
        if (gr < n) v = ((const float4*)A)[gr * 32 + k4];
        ((float4*)(As + row * FD))[k4 ^ ((row >> 2) & 7)] = v;
    }
    __syncthreads();

    int warp = tid >> 5, lane = tid & 31;
    int wr = warp & 1, wc = warp >> 1;        // wc: 0..3
    int lr = lane >> 2, lc = lane & 3;
    int rbase = wr * 32 + lr * 4;             // ((rbase+j)>>2)&7 == lr
    int cbase = wc * 32 + lc * 8;

    const float4* As0 = (const float4*)(As + (rbase + 0) * FD);
    const float4* As1 = (const float4*)(As + (rbase + 1) * FD);
    const float4* As2 = (const float4*)(As + (rbase + 2) * FD);
    const float4* As3 = (const float4*)(As + (rbase + 3) * FD);

    ull acc[16];
#pragma unroll
    for (int i = 0; i < 16; i++) acc[i] = 0ull;

#pragma unroll 2
    for (int k4 = 0; k4 < 32; k4++) {
        float4 a0 = As0[k4 ^ lr];
        float4 a1 = As1[k4 ^ lr];
        float4 a2 = As2[k4 ^ lr];
        float4 a3 = As3[k4 ^ lr];
        const float* a0f = (const float*)&a0;
        const float* a1f = (const float*)&a1;
        const float* a2f = (const float*)&a2;
        const float* a3f = (const float*)&a3;
#pragma unroll
        for (int kk = 0; kk < 4; kk++) {
            const ulonglong2* wrow = (const ulonglong2*)(Ws + (4 * k4 + kk) * FD + cbase);
            ulonglong2 wA = wrow[0];          // cols cbase..cbase+3
            ulonglong2 wB = wrow[1];          // cols cbase+4..cbase+7
            ull p0 = pk2(a0f[kk]);
            ull p1 = pk2(a1f[kk]);
            ull p2 = pk2(a2f[kk]);
            ull p3 = pk2(a3f[kk]);
            acc[0]  = ffma2(p0, wA.x, acc[0]);   acc[1]  = ffma2(p0, wA.y, acc[1]);
            acc[2]  = ffma2(p0, wB.x, acc[2]);   acc[3]  = ffma2(p0, wB.y, acc[3]);
            acc[4]  = ffma2(p1, wA.x, acc[4]);   acc[5]  = ffma2(p1, wA.y, acc[5]);
            acc[6]  = ffma2(p1, wB.x, acc[6]);   acc[7]  = ffma2(p1, wB.y, acc[7]);
            acc[8]  = ffma2(p2, wA.x, acc[8]);   acc[9]  = ffma2(p2, wA.y, acc[9]);
            acc[10] = ffma2(p2, wB.x, acc[10]);  acc[11] = ffma2(p2, wB.y, acc[11]);
            acc[12] = ffma2(p3, wA.x, acc[12]);  acc[13] = ffma2(p3, wA.y, acc[13]);
            acc[14] = ffma2(p3, wB.x, acc[14]);  acc[15] = ffma2(p3, wB.y, acc[15]);
        }
    }

#pragma unroll
    for (int j = 0; j < 4; j++) {
        int gr = rowBase + rbase + j;
        if (gr < n) {
            float sc = scaled ? g_dinv[gr] : 1.0f;
            float2 q0 = upk2(acc[j * 4 + 0]), q1 = upk2(acc[j * 4 + 1]);
            float2 q2 = upk2(acc[j * 4 + 2]), q3 = upk2(acc[j * 4 + 3]);
            ((float4*)out)[gr * 32 + (cbase >> 2)] =
                make_float4(q0.x * sc, q0.y * sc, q1.x * sc, q1.y * sc);
            ((float4*)out)[gr * 32 + (cbase >> 2) + 1] =
                make_float4(q2.x * sc, q2.y * sc, q3.x * sc, q3.y * sc);
        }
    }
}

// ---------- aggregation 1 (node range [n0, n1)) ----------
// S = hs UNSCALED.  out[d] = dinv[d]*( dinv[d]*hs[d] + sum_src dinv[src]*hs[src] ) + b1
__global__ void k_agg1(const float* __restrict__ S,
                       const float* __restrict__ bias,
                       float* __restrict__ out, int n0, int n1) {
    int gw = n0 + ((blockIdx.x * blockDim.x + threadIdx.x) >> 5);
    if (gw >= n1) return;
    int lane = threadIdx.x & 31;
    const float4* Sv = (const float4*)S;
    int beg = g_rowptr[gw], end = g_rowptr[gw + 1];
    float dd = g_dinv[gw];
    float4 sv = Sv[gw * 32 + lane];
    float4 a = make_float4(sv.x * dd, sv.y * dd, sv.z * dd, sv.w * dd);
#pragma unroll 4
    for (int e = beg; e < end; e++) {
        int s = __ldg(&g_esrc[e]);
        float ds = __ldg(&g_dinv[s]);
        float4 v = Sv[s * 32 + lane];
        a.x = fmaf(v.x, ds, a.x);
        a.y = fmaf(v.y, ds, a.y);
        a.z = fmaf(v.z, ds, a.z);
        a.w = fmaf(v.w, ds, a.w);
    }
    float4 b = ((const float4*)bias)[lane];
    ((float4*)out)[gw * 32 + lane] =
        make_float4(a.x * dd + b.x, a.y * dd + b.y, a.z * dd + b.z, a.w * dd + b.w);
}

// ---------- aggregation 2 + reparametrize ----------
// S rows pre-scaled by dinv[src]; layout [mu(64)|logstd(64)].
__global__ void k_agg2(const float* __restrict__ S,
                       const float* __restrict__ bmu,
                       const float* __restrict__ bls,
                       const float* __restrict__ initd,
                       float* __restrict__ out, int n) {
    int gw = (blockIdx.x * blockDim.x + threadIdx.x) >> 5;
    if (gw >= n) return;
    int lane = threadIdx.x & 31;
    const float4* Sv = (const float4*)S;
    int beg = g_rowptr[gw], end = g_rowptr[gw + 1];
    float4 a = Sv[gw * 32 + lane];
#pragma unroll 4
    for (int e = beg; e < end; e++) {
        int s = __ldg(&g_esrc[e]);
        float4 v = Sv[s * 32 + lane];
        a.x += v.x; a.y += v.y; a.z += v.z; a.w += v.w;
    }
    float sc = g_dinv[gw];
    a.x *= sc; a.y *= sc; a.z *= sc; a.w *= sc;

    float ox = __shfl_xor_sync(0xffffffffu, a.x, 16);
    float oy = __shfl_xor_sync(0xffffffffu, a.y, 16);
    float oz = __shfl_xor_sync(0xffffffffu, a.z, 16);
    float ow = __shfl_xor_sync(0xffffffffu, a.w, 16);

    if (lane < 16) {
        float4 bm = ((const float4*)bmu)[lane];
        float4 bl = ((const float4*)bls)[lane];
        float4 iv = ((const float4*)initd)[gw * 16 + lane];
        float4 r;
        r.x = (a.x + bm.x) + iv.x * expf(ox + bl.x);
        r.y = (a.y + bm.y) + iv.y * expf(oy + bl.y);
        r.z = (a.z + bm.z) + iv.z * expf(oz + bl.z);
        r.w = (a.w + bm.w) + iv.w * expf(ow + bl.w);
        ((float4*)out)[gw * 16 + lane] = r;
    }
}

#define SMEM_GEMM ((64 * FD + FD * FD) * (int)sizeof(float))   // 96KB

extern "C" void kernel_launch(void* const* d_in, const int* in_sizes, int n_in,
                              void* d_out, int out_size) {
    const float* x     = (const float*)d_in[0];
    const int*   ei    = (const int*)d_in[1];
    const float* initd = (const float*)d_in[2];
    const float* W1    = (const float*)d_in[3];
    const float* b1    = (const float*)d_in[4];
    const float* Wmu   = (const float*)d_in[5];
    const float* bmu   = (const float*)d_in[6];
    const float* Wls   = (const float*)d_in[7];
    const float* bls   = (const float*)d_in[8];
    float* out = (float*)d_out;

    int n = in_sizes[0] / FD;
    int E = in_sizes[1] / 2;
    const int* src = ei;
    const int* dst = ei + E;

    void *pA = nullptr, *pB = nullptr, *pC = nullptr;
    cudaGetSymbolAddress(&pA, g_bufA);
    cudaGetSymbolAddress(&pB, g_bufB);
    cudaGetSymbolAddress(&pC, g_cnt);
    float* bufA = (float*)pA;
    float* bufB = (float*)pB;

    cudaFuncSetAttribute(k_gemm, cudaFuncAttributeMaxDynamicSharedMemorySize, SMEM_GEMM);

    int nblk = (n + SCHUNK - 1) / SCHUNK;
    int nh = (((n / 2) + 63) / 64) * 64;       // half split, 64-row aligned
    if (nh > n) nh = n;

    // Fork a NonBlocking stream for prep / pipe-1. Streams/events deliberately
    // NOT destroyed (destroying mid-capture is illegal; launch runs few times).
    static cudaStream_t s2 = nullptr;
    static cudaEvent_t evF = nullptr, evPrep = nullptr, evG1 = nullptr, evB2 = nullptr;
    if (!s2) {
        cudaStreamCreateWithFlags(&s2, cudaStreamNonBlocking);
        cudaEventCreateWithFlags(&evF, cudaEventDisableTiming);
        cudaEventCreateWithFlags(&evPrep, cudaEventDisableTiming);
        cudaEventCreateWithFlags(&evG1, cudaEventDisableTiming);
        cudaEventCreateWithFlags(&evB2, cudaEventDisableTiming);
    }

    cudaEventRecord(evF, 0);
    cudaStreamWaitEvent(s2, evF, 0);

    // prep chain on s2 (kernels 0..2 issued first, then GEMM1 at slot 3 for ncu)
    cudaMemsetAsync(pC, 0, n * sizeof(int), s2);
    k_count<<<(E + 255) / 256, 256, 0, s2>>>(dst, E);            // k0
    k_scan1<<<nblk, SCHUNK, 0, s2>>>(n);                         // k1
    k_scan2<<<1, SCHUNK, 0, s2>>>(nblk);                         // k2

    // GEMM1 (full) on default stream, concurrent with prep
    k_gemm<<<(n + 63) / 64, 256, SMEM_GEMM>>>(x, W1, W1 + OUTF, FD, 0, bufA, n, 0);  // k3 (ncu)
    cudaEventRecord(evG1, 0);

    k_rows<<<(n + 255) / 256, 256, 0, s2>>>(n, E);
    k_scatter<<<(E + 255) / 256, 256, 0, s2>>>(src, dst, E);
    cudaEventRecord(evPrep, s2);

    // ---- two pipes: agg1 -> GEMM2 on disjoint node halves ----
    // pipe 0 (default stream): [0, nh)
    cudaStreamWaitEvent(0, evPrep, 0);
    k_agg1<<<(nh * 32 + 255) / 256, 256>>>(bufA, b1, bufB, 0, nh);
    k_gemm<<<(nh + 63) / 64, 256, SMEM_GEMM>>>(bufB, Wmu, Wls, OUTF, 1, bufA, nh, 0);

    // pipe 1 (s2): [nh, n)  (prep already ordered on s2; needs GEMM1 too)
    cudaStreamWaitEvent(s2, evG1, 0);
    if (n > nh) {
        k_agg1<<<((n - nh) * 32 + 255) / 256, 256, 0, s2>>>(bufA, b1, bufB, nh, n);
        k_gemm<<<(n - nh + 63) / 64, 256, SMEM_GEMM, s2>>>(bufB, Wmu, Wls, OUTF, 1, bufA, n, nh);
    }
    cudaEventRecord(evB2, s2);
    cudaStreamWaitEvent(0, evB2, 0);

    // agg2 + reparametrize (needs all of GEMM2)
    k_agg2<<<(n * 32 + 255) / 256, 256>>>(bufA, bmu, bls, initd, out, n);
}